// round 1
// baseline (speedup 1.0000x reference)
#include <cuda_runtime.h>

// SphericalVectorPool: B=1, N=2048, A=2048, S=16 scales, out [A, 4*S] f32.
//
// Kernel 1 (svp_main): all-pairs accumulation. grid = (A/128, NSPLIT).
//   thread = one output point a; loops over a CHUNK of input points held in
//   a float4 smem tile; 64 register accumulators (4 channels x 16 scales).
//   Writes partials to __device__ scratch [NSPLIT][64ch][A] (coalesced).
// Kernel 2 (svp_reduce): sums NSPLIT partials, applies r_norms * a_norms
//   scaling (read from inputs), writes final [A, 64] layout.

namespace {
constexpr int A_TOTAL = 2048;
constexpr int N_TOTAL = 2048;
constexpr int S       = 16;
constexpr int NCH     = 4 * S;              // 64 output channels
constexpr int NSPLIT  = 32;                 // N-dimension partitions
constexpr int CHUNK   = N_TOTAL / NSPLIT;   // 64 input points per CTA
constexpr int BLOCK   = 128;
constexpr float LOG2E = 1.4426950408889634f;
}

// 32 * 64 * 2048 * 4B = 16 MB scratch for partial sums.
__device__ float g_partial[NSPLIT][NCH][A_TOTAL];

__device__ __forceinline__ float ex2f(float x) {
    float y;
    asm("ex2.approx.ftz.f32 %0, %1;" : "=f"(y) : "f"(x));
    return y;
}

__global__ __launch_bounds__(BLOCK, 4) void svp_main(
    const float* __restrict__ f,
    const float* __restrict__ coords,
    const float* __restrict__ out_coords,
    const float* __restrict__ mu)
{
    __shared__ float4 tile[CHUNK];

    const int a  = blockIdx.x * BLOCK + threadIdx.x;
    const int n0 = blockIdx.y * CHUNK;

    // Stage this CTA's chunk of input points into smem as (x, y, z, f).
    for (int j = threadIdx.x; j < CHUNK; j += BLOCK) {
        const int n = n0 + j;
        tile[j] = make_float4(coords[3 * n + 0], coords[3 * n + 1],
                              coords[3 * n + 2], f[n]);
    }

    // Per-scale exp2 argument factors: -log2(e) * mu_s, kept in registers.
    float nmu[S];
    #pragma unroll
    for (int s = 0; s < S; ++s) nmu[s] = -LOG2E * mu[s];

    const float Rx = out_coords[3 * a + 0];
    const float Ry = out_coords[3 * a + 1];
    const float Rz = out_coords[3 * a + 2];

    float a0[S], a1x[S], a1y[S], a1z[S];
    #pragma unroll
    for (int s = 0; s < S; ++s) {
        a0[s] = 0.f; a1x[s] = 0.f; a1y[s] = 0.f; a1z[s] = 0.f;
    }

    __syncthreads();

    for (int j = 0; j < CHUNK; ++j) {
        const float4 p = tile[j];                 // broadcast LDS.128
        const float dx = p.x - Rx;
        const float dy = p.y - Ry;
        const float dz = p.z - Rz;
        const float r2   = fmaf(dx, dx, fmaf(dy, dy, dz * dz));
        const float rinv = rsqrtf(r2);            // MUFU.RSQ
        const float r    = r2 * rinv;
        const float fi   = p.w;
        const float g    = fi * rinv;
        const float gx = g * dx, gy = g * dy, gz = g * dz;

        #pragma unroll
        for (int s = 0; s < S; ++s) {
            const float e = ex2f(r * nmu[s]);     // exp(-mu_s * r)
            a0[s]  = fmaf(e, fi, a0[s]);          // l=0
            a1x[s] = fmaf(e, gx, a1x[s]);         // l=1, d=x
            a1y[s] = fmaf(e, gy, a1y[s]);
            a1z[s] = fmaf(e, gz, a1z[s]);
        }
    }

    // Coalesced partial stores: channel-major, a contiguous.
    const int y = blockIdx.y;
    #pragma unroll
    for (int s = 0; s < S; ++s) {
        g_partial[y][s][a]             = a0[s];
        g_partial[y][S + 3 * s + 0][a] = a1x[s];
        g_partial[y][S + 3 * s + 1][a] = a1y[s];
        g_partial[y][S + 3 * s + 2][a] = a1z[s];
    }
}

__global__ void svp_reduce(
    float* __restrict__ out,
    const float* __restrict__ r_norms,
    const float* __restrict__ an0,
    const float* __restrict__ an1)
{
    const int idx = blockIdx.x * blockDim.x + threadIdx.x;  // over NCH * A
    const int c = idx / A_TOTAL;
    const int a = idx - c * A_TOTAL;

    float sum = 0.f;
    #pragma unroll
    for (int y = 0; y < NSPLIT; ++y) sum += g_partial[y][c][a];

    float scale;
    if (c < S) {
        scale = r_norms[c] * an0[0];
    } else {
        const int c2 = c - S;
        const int s  = c2 / 3;
        const int d  = c2 - 3 * s;
        scale = r_norms[s] * an1[d];
    }
    out[a * NCH + c] = sum * scale;
}

extern "C" void kernel_launch(void* const* d_in, const int* in_sizes, int n_in,
                              void* d_out, int out_size) {
    const float* f          = (const float*)d_in[0];
    const float* coords     = (const float*)d_in[1];
    const float* out_coords = (const float*)d_in[2];
    const float* mu         = (const float*)d_in[3];
    const float* r_norms    = (const float*)d_in[4];
    const float* an0        = (const float*)d_in[5];
    const float* an1        = (const float*)d_in[6];
    (void)in_sizes; (void)n_in; (void)out_size;

    dim3 grid(A_TOTAL / BLOCK, NSPLIT);
    svp_main<<<grid, BLOCK>>>(f, coords, out_coords, mu);

    const int total = NCH * A_TOTAL;
    svp_reduce<<<total / 256, 256>>>((float*)d_out, r_norms, an0, an1);
}